// round 7
// baseline (speedup 1.0000x reference)
#include <cuda_runtime.h>

#define KSEG 512
#define DFEAT 256
#define HID 64
#define OUTC 32
#define MAXN 1048576
#define NB   1184         // hist/scatter blocks (8 per SM on 148 SMs)
#define SPLIT 4           // reduce CTAs per segment
#define CPT 5             // blocks per thread in seg-scan (ceil(1184/256))
#define STAGE 512         // perm indices staged in shared per chunk

__device__ int g_blockhist[NB * KSEG];   // pass A: counts; pass B: per-(block,seg) base
__device__ int g_count[KSEG];
__device__ int g_offsets[KSEG + 1];
__device__ int g_perm[MAXN];
__device__ float g_part[SPLIT * KSEG * DFEAT];   // feature partial sums
__device__ float g_cpart[SPLIT * KSEG * 3];      // coord partial sums

// ---------------------------------------------------------------- pass A: per-block histogram
__global__ void __launch_bounds__(256) hist_kernel(const int* __restrict__ ids, int n, int chunk) {
    __shared__ int sh[KSEG];
    for (int i = threadIdx.x; i < KSEG; i += 256) sh[i] = 0;
    __syncthreads();
    int b = blockIdx.x;
    int lo = b * chunk;
    int hi = min(lo + chunk, n);
    for (int i = lo + threadIdx.x; i < hi; i += 256) {
        int s = ids[i];
        if (s >= 0) atomicAdd(&sh[s], 1);
    }
    __syncthreads();
    for (int i = threadIdx.x; i < KSEG; i += 256)
        g_blockhist[b * KSEG + i] = sh[i];
}

// ---------------------------------------------------------------- pass B1: per-segment scan over blocks
// grid = KSEG (1 CTA per segment), 256 threads, CPT blocks/thread.
__global__ void __launch_bounds__(256) segscan_kernel() {
    int s = blockIdx.x;
    int t = threadIdx.x;
    int b0 = t * CPT;
    int v[CPT];
    int local = 0;
#pragma unroll
    for (int k = 0; k < CPT; k++) {
        int b = b0 + k;
        v[k] = (b < NB) ? g_blockhist[b * KSEG + s] : 0;
        local += v[k];
    }
    __shared__ int sh[256];
    sh[t] = local;
    __syncthreads();
    for (int off = 1; off < 256; off <<= 1) {
        int tmp = (t >= off) ? sh[t - off] : 0;
        int cur = sh[t];
        __syncthreads();
        sh[t] = cur + tmp;
        __syncthreads();
    }
    int run = sh[t] - local;   // exclusive prefix
#pragma unroll
    for (int k = 0; k < CPT; k++) {
        int b = b0 + k;
        if (b < NB) g_blockhist[b * KSEG + s] = run;
        run += v[k];
    }
    if (t == 255) g_count[s] = sh[255];
}

// ---------------------------------------------------------------- pass B2: segment-offset scan (1 CTA)
__global__ void __launch_bounds__(KSEG) offscan_kernel() {
    int s = threadIdx.x;
    int val = g_count[s];
    __shared__ int sh[KSEG];
    sh[s] = val;
    __syncthreads();
    for (int off = 1; off < KSEG; off <<= 1) {
        int tmp = (s >= off) ? sh[s - off] : 0;
        int cur = sh[s];
        __syncthreads();
        sh[s] = cur + tmp;
        __syncthreads();
    }
    g_offsets[s] = sh[s] - val;
    if (s == KSEG - 1) g_offsets[KSEG] = sh[s];
}

// ---------------------------------------------------------------- pass C: scatter (shared cursors)
__global__ void __launch_bounds__(256) scatter_kernel(const int* __restrict__ ids, int n, int chunk) {
    __shared__ int cur[KSEG];
    int b = blockIdx.x;
    for (int i = threadIdx.x; i < KSEG; i += 256)
        cur[i] = g_offsets[i] + g_blockhist[b * KSEG + i];
    __syncthreads();
    int lo = b * chunk;
    int hi = min(lo + chunk, n);
    for (int i = lo + threadIdx.x; i < hi; i += 256) {
        int s = ids[i];
        if (s >= 0) {
            int pos = atomicAdd(&cur[s], 1);
            g_perm[pos] = i;
        }
    }
}

// ---------------------------------------------------------------- split reduce (partials, no atomics)
// grid = KSEG*SPLIT = 2048 CTAs of 128 threads: 16 CTAs/SM -> single full wave.
// 64 col-groups (float4) x 2 row slots; perm staged through shared.
__global__ void __launch_bounds__(128, 16) reduce_kernel(const float4* __restrict__ feat4,
                                                         const float* __restrict__ coords) {
    int bid = blockIdx.x;
    int s = bid >> 2;          // segment
    int p = bid & (SPLIT - 1); // part
    int start = g_offsets[s];
    int end   = g_offsets[s + 1];
    int len   = end - start;
    int per   = (len + SPLIT - 1) / SPLIT;
    int lo = start + p * per;
    int hi = min(lo + per, end);

    int t  = threadIdx.x;
    int cg = t & 63;    // column group: cols [4cg, 4cg+3]
    int rs = t >> 6;    // row slot 0..1

    __shared__ int sperm[STAGE];
    float4 acc = make_float4(0.f, 0.f, 0.f, 0.f);
    float cx = 0.f, cy = 0.f, cz = 0.f;

    for (int base = lo; base < hi; base += STAGE) {
        int m = min(STAGE, hi - base);
        __syncthreads();
        for (int i = t; i < m; i += 128) sperm[i] = g_perm[base + i];
        __syncthreads();

        // feature rows: thread handles rows rs, rs+2, ... ; 4 rows in flight
        int j = rs;
        for (; j + 6 < m; j += 8) {
            int i0 = sperm[j];
            int i1 = sperm[j + 2];
            int i2 = sperm[j + 4];
            int i3 = sperm[j + 6];
            float4 v0 = feat4[(size_t)i0 * 64 + cg];
            float4 v1 = feat4[(size_t)i1 * 64 + cg];
            float4 v2 = feat4[(size_t)i2 * 64 + cg];
            float4 v3 = feat4[(size_t)i3 * 64 + cg];
            acc.x += (v0.x + v1.x) + (v2.x + v3.x);
            acc.y += (v0.y + v1.y) + (v2.y + v3.y);
            acc.z += (v0.z + v1.z) + (v2.z + v3.z);
            acc.w += (v0.w + v1.w) + (v2.w + v3.w);
        }
        for (; j < m; j += 2) {
            int i0 = sperm[j];
            float4 v0 = feat4[(size_t)i0 * 64 + cg];
            acc.x += v0.x; acc.y += v0.y; acc.z += v0.z; acc.w += v0.w;
        }

        // coords: strided over all 128 threads
        for (int jj = t; jj < m; jj += 128) {
            int i = sperm[jj];
            cx += coords[3 * (size_t)i + 0];
            cy += coords[3 * (size_t)i + 1];
            cz += coords[3 * (size_t)i + 2];
        }
    }

    __shared__ float4 shv[128];
    shv[t] = acc;
    __syncthreads();
    if (rs == 0) {
        float4 a = shv[cg], b = shv[cg + 64];
        float4 r;
        r.x = a.x + b.x; r.y = a.y + b.y; r.z = a.z + b.z; r.w = a.w + b.w;
        ((float4*)g_part)[((size_t)p * KSEG + s) * 64 + cg] = r;
    }

    __shared__ float shx[128], shy[128], shz[128];
    shx[t] = cx; shy[t] = cy; shz[t] = cz;
    __syncthreads();
    for (int off = 64; off > 0; off >>= 1) {
        if (t < off) {
            shx[t] += shx[t + off];
            shy[t] += shy[t + off];
            shz[t] += shz[t + off];
        }
        __syncthreads();
    }
    if (t == 0) {
        g_cpart[((size_t)p * KSEG + s) * 3 + 0] = shx[0];
        g_cpart[((size_t)p * KSEG + s) * 3 + 1] = shy[0];
        g_cpart[((size_t)p * KSEG + s) * 3 + 2] = shz[0];
    }
}

// ---------------------------------------------------------------- combine + centroid + MLP (fused)
// grid = KSEG, 256 threads.
__global__ void __launch_bounds__(256) combine_kernel(const float* __restrict__ W1,
                                                      const float* __restrict__ W2,
                                                      const float* __restrict__ W3,
                                                      const float* __restrict__ b3,
                                                      float* __restrict__ emb,
                                                      float* __restrict__ cent,
                                                      float* __restrict__ out) {
    int s = blockIdx.x;
    int t = threadIdx.x;
    int cnt = g_offsets[s + 1] - g_offsets[s];
    float denom = 1.0f / (float)(cnt > 0 ? cnt : 1);

    __shared__ float e[DFEAT];
    float v = 0.f;
#pragma unroll
    for (int p = 0; p < SPLIT; p++)
        v += g_part[((size_t)p * KSEG + s) * DFEAT + t];
    v *= denom;
    e[t] = v;
    emb[(size_t)s * DFEAT + t] = v;

    if (t < 3) {
        float c = 0.f;
#pragma unroll
        for (int p = 0; p < SPLIT; p++)
            c += g_cpart[((size_t)p * KSEG + s) * 3 + t];
        cent[s * 3 + t] = c * denom;
    }
    __syncthreads();

    __shared__ float h1[HID];
    __shared__ float h2[HID];
    if (t < HID) {
        float a = 0.f;
#pragma unroll 8
        for (int k = 0; k < DFEAT; k++) a += e[k] * W1[k * HID + t];
        h1[t] = fmaxf(a, 0.f);
    }
    __syncthreads();
    if (t < HID) {
        float b = 0.f;
#pragma unroll 8
        for (int k = 0; k < HID; k++) b += h1[k] * W2[k * HID + t];
        h2[t] = fmaxf(b, 0.f);
    }
    __syncthreads();
    if (t < OUTC) {
        float c = b3[t];
#pragma unroll 8
        for (int k = 0; k < HID; k++) c += h2[k] * W3[k * OUTC + t];
        out[(size_t)s * OUTC + t] = c;
    }
}

// ---------------------------------------------------------------- launch
extern "C" void kernel_launch(void* const* d_in, const int* in_sizes, int n_in,
                              void* d_out, int out_size) {
    const float* feat   = (const float*)d_in[0];
    const float* coords = (const float*)d_in[1];
    const int*   ids    = (const int*)d_in[2];

    int wi = 3;
    if (n_in >= 8 && in_sizes[3] == 1) wi = 4;
    const float* W1 = (const float*)d_in[wi + 0];
    const float* W2 = (const float*)d_in[wi + 1];
    const float* W3 = (const float*)d_in[wi + 2];
    const float* b3 = (const float*)d_in[wi + 3];

    int n = in_sizes[0] / DFEAT;
    int chunk = (n + NB - 1) / NB;

    float* out  = (float*)d_out;
    float* emb  = out;                           // [K, 256]
    float* cent = out + (size_t)KSEG * DFEAT;    // [K, 3]
    float* mlp  = cent + (size_t)KSEG * 3;       // [K, 32]
    (void)out_size;

    hist_kernel<<<NB, 256>>>(ids, n, chunk);
    segscan_kernel<<<KSEG, 256>>>();
    offscan_kernel<<<1, KSEG>>>();
    scatter_kernel<<<NB, 256>>>(ids, n, chunk);
    reduce_kernel<<<KSEG * SPLIT, 128>>>((const float4*)feat, coords);
    combine_kernel<<<KSEG, 256>>>(W1, W2, W3, b3, emb, cent, mlp);
}

// round 9
// speedup vs baseline: 1.0182x; 1.0182x over previous
#include <cuda_runtime.h>

#define KSEG 512
#define DFEAT 256
#define HID 64
#define OUTC 32
#define MAXN 1048576
#define NB   592          // hist/scatter blocks (4 per SM on 148 SMs)
#define SPLIT 4           // reduce CTAs per segment
#define CPT 3             // blocks per thread in seg-scan (ceil(592/256))

__device__ int g_blockhist[NB * KSEG];   // pass A: counts; pass B: per-(block,seg) base
__device__ int g_count[KSEG];
__device__ int g_offsets[KSEG + 1];
__device__ int g_perm[MAXN];
__device__ float g_part[SPLIT * KSEG * DFEAT];   // feature partial sums
__device__ float g_cpart[SPLIT * KSEG * 3];      // coord partial sums

// ---------------------------------------------------------------- pass A: per-block histogram (int4)
__global__ void __launch_bounds__(256) hist_kernel(const int* __restrict__ ids, int n, int chunk) {
    __shared__ int sh[KSEG];
    for (int i = threadIdx.x; i < KSEG; i += 256) sh[i] = 0;
    __syncthreads();
    int b = blockIdx.x;
    int lo = b * chunk;                 // chunk is a multiple of 4
    int hi = min(lo + chunk, n);
    int nv = (hi - lo) >> 2;            // full int4s
    const int4* ids4 = (const int4*)(ids + lo);
    for (int i = threadIdx.x; i < nv; i += 256) {
        int4 v = ids4[i];
        if (v.x >= 0) atomicAdd(&sh[v.x], 1);
        if (v.y >= 0) atomicAdd(&sh[v.y], 1);
        if (v.z >= 0) atomicAdd(&sh[v.z], 1);
        if (v.w >= 0) atomicAdd(&sh[v.w], 1);
    }
    // tail (hi-lo not multiple of 4)
    for (int i = lo + (nv << 2) + threadIdx.x; i < hi; i += 256) {
        int s = ids[i];
        if (s >= 0) atomicAdd(&sh[s], 1);
    }
    __syncthreads();
    for (int i = threadIdx.x; i < KSEG; i += 256)
        g_blockhist[b * KSEG + i] = sh[i];
}

// ---------------------------------------------------------------- pass B1: per-segment scan over blocks
// grid = KSEG (1 CTA per segment), 256 threads, CPT blocks/thread.
__global__ void __launch_bounds__(256) segscan_kernel() {
    int s = blockIdx.x;
    int t = threadIdx.x;
    int b0 = t * CPT;
    int v[CPT];
    int local = 0;
#pragma unroll
    for (int k = 0; k < CPT; k++) {
        int b = b0 + k;
        v[k] = (b < NB) ? g_blockhist[b * KSEG + s] : 0;
        local += v[k];
    }
    __shared__ int sh[256];
    sh[t] = local;
    __syncthreads();
    for (int off = 1; off < 256; off <<= 1) {
        int tmp = (t >= off) ? sh[t - off] : 0;
        int cur = sh[t];
        __syncthreads();
        sh[t] = cur + tmp;
        __syncthreads();
    }
    int run = sh[t] - local;   // exclusive prefix
#pragma unroll
    for (int k = 0; k < CPT; k++) {
        int b = b0 + k;
        if (b < NB) g_blockhist[b * KSEG + s] = run;
        run += v[k];
    }
    if (t == 255) g_count[s] = sh[255];
}

// ---------------------------------------------------------------- pass B2: segment-offset scan (1 CTA)
__global__ void __launch_bounds__(KSEG) offscan_kernel() {
    int s = threadIdx.x;
    int val = g_count[s];
    __shared__ int sh[KSEG];
    sh[s] = val;
    __syncthreads();
    for (int off = 1; off < KSEG; off <<= 1) {
        int tmp = (s >= off) ? sh[s - off] : 0;
        int cur = sh[s];
        __syncthreads();
        sh[s] = cur + tmp;
        __syncthreads();
    }
    g_offsets[s] = sh[s] - val;
    if (s == KSEG - 1) g_offsets[KSEG] = sh[s];
}

// ---------------------------------------------------------------- pass C: scatter (shared cursors, int4)
__global__ void __launch_bounds__(256) scatter_kernel(const int* __restrict__ ids, int n, int chunk) {
    __shared__ int cur[KSEG];
    int b = blockIdx.x;
    for (int i = threadIdx.x; i < KSEG; i += 256)
        cur[i] = g_offsets[i] + g_blockhist[b * KSEG + i];
    __syncthreads();
    int lo = b * chunk;
    int hi = min(lo + chunk, n);
    int nv = (hi - lo) >> 2;
    const int4* ids4 = (const int4*)(ids + lo);
    for (int i = threadIdx.x; i < nv; i += 256) {
        int4 v = ids4[i];
        int base = lo + (i << 2);
        if (v.x >= 0) g_perm[atomicAdd(&cur[v.x], 1)] = base;
        if (v.y >= 0) g_perm[atomicAdd(&cur[v.y], 1)] = base + 1;
        if (v.z >= 0) g_perm[atomicAdd(&cur[v.z], 1)] = base + 2;
        if (v.w >= 0) g_perm[atomicAdd(&cur[v.w], 1)] = base + 3;
    }
    for (int i = lo + (nv << 2) + threadIdx.x; i < hi; i += 256) {
        int s = ids[i];
        if (s >= 0) g_perm[atomicAdd(&cur[s], 1)] = i;
    }
}

// ---------------------------------------------------------------- split reduce (R6 winner, untouched)
// grid = KSEG*SPLIT. 256 threads: 64 col-groups (float4) x 4 row slots, 4-deep unroll.
__global__ void __launch_bounds__(256) reduce_kernel(const float4* __restrict__ feat4,
                                                     const float* __restrict__ coords) {
    int bid = blockIdx.x;
    int s = bid >> 2;          // segment
    int p = bid & (SPLIT - 1); // part
    int start = g_offsets[s];
    int end   = g_offsets[s + 1];
    int len   = end - start;
    int per   = (len + SPLIT - 1) / SPLIT;
    int lo = start + p * per;
    int hi = min(lo + per, end);

    int t  = threadIdx.x;
    int cg = t & 63;    // column group: cols [4cg, 4cg+3]
    int rs = t >> 6;    // row slot 0..3

    float4 acc = make_float4(0.f, 0.f, 0.f, 0.f);
    int j = lo + rs;
    for (; j + 12 < hi; j += 16) {
        int i0 = g_perm[j];
        int i1 = g_perm[j + 4];
        int i2 = g_perm[j + 8];
        int i3 = g_perm[j + 12];
        float4 v0 = feat4[(size_t)i0 * 64 + cg];
        float4 v1 = feat4[(size_t)i1 * 64 + cg];
        float4 v2 = feat4[(size_t)i2 * 64 + cg];
        float4 v3 = feat4[(size_t)i3 * 64 + cg];
        acc.x += (v0.x + v1.x) + (v2.x + v3.x);
        acc.y += (v0.y + v1.y) + (v2.y + v3.y);
        acc.z += (v0.z + v1.z) + (v2.z + v3.z);
        acc.w += (v0.w + v1.w) + (v2.w + v3.w);
    }
    for (; j < hi; j += 4) {
        int i0 = g_perm[j];
        float4 v0 = feat4[(size_t)i0 * 64 + cg];
        acc.x += v0.x; acc.y += v0.y; acc.z += v0.z; acc.w += v0.w;
    }

    __shared__ float4 shv[256];
    shv[t] = acc;
    __syncthreads();
    if (rs == 0) {
        float4 a = shv[cg], b = shv[cg + 64], c = shv[cg + 128], d = shv[cg + 192];
        float4 r;
        r.x = (a.x + b.x) + (c.x + d.x);
        r.y = (a.y + b.y) + (c.y + d.y);
        r.z = (a.z + b.z) + (c.z + d.z);
        r.w = (a.w + b.w) + (c.w + d.w);
        ((float4*)g_part)[((size_t)p * KSEG + s) * 64 + cg] = r;
    }

    // coords partial
    float cx = 0.f, cy = 0.f, cz = 0.f;
    for (int jj = lo + t; jj < hi; jj += 256) {
        int i = g_perm[jj];
        cx += coords[3 * (size_t)i + 0];
        cy += coords[3 * (size_t)i + 1];
        cz += coords[3 * (size_t)i + 2];
    }
    __shared__ float shx[256], shy[256], shz[256];
    shx[t] = cx; shy[t] = cy; shz[t] = cz;
    __syncthreads();
    for (int off = 128; off > 0; off >>= 1) {
        if (t < off) {
            shx[t] += shx[t + off];
            shy[t] += shy[t + off];
            shz[t] += shz[t + off];
        }
        __syncthreads();
    }
    if (t == 0) {
        g_cpart[((size_t)p * KSEG + s) * 3 + 0] = shx[0];
        g_cpart[((size_t)p * KSEG + s) * 3 + 1] = shy[0];
        g_cpart[((size_t)p * KSEG + s) * 3 + 2] = shz[0];
    }
}

// ---------------------------------------------------------------- combine + centroid + MLP (fused)
// grid = KSEG, 256 threads.
__global__ void __launch_bounds__(256) combine_kernel(const float* __restrict__ W1,
                                                      const float* __restrict__ W2,
                                                      const float* __restrict__ W3,
                                                      const float* __restrict__ b3,
                                                      float* __restrict__ emb,
                                                      float* __restrict__ cent,
                                                      float* __restrict__ out) {
    int s = blockIdx.x;
    int t = threadIdx.x;
    int cnt = g_offsets[s + 1] - g_offsets[s];
    float denom = 1.0f / (float)(cnt > 0 ? cnt : 1);

    __shared__ float e[DFEAT];
    float v = 0.f;
#pragma unroll
    for (int p = 0; p < SPLIT; p++)
        v += g_part[((size_t)p * KSEG + s) * DFEAT + t];
    v *= denom;
    e[t] = v;
    emb[(size_t)s * DFEAT + t] = v;

    if (t < 3) {
        float c = 0.f;
#pragma unroll
        for (int p = 0; p < SPLIT; p++)
            c += g_cpart[((size_t)p * KSEG + s) * 3 + t];
        cent[s * 3 + t] = c * denom;
    }
    __syncthreads();

    __shared__ float h1[HID];
    __shared__ float h2[HID];
    if (t < HID) {
        float a = 0.f;
#pragma unroll 8
        for (int k = 0; k < DFEAT; k++) a += e[k] * W1[k * HID + t];
        h1[t] = fmaxf(a, 0.f);
    }
    __syncthreads();
    if (t < HID) {
        float b = 0.f;
#pragma unroll 8
        for (int k = 0; k < HID; k++) b += h1[k] * W2[k * HID + t];
        h2[t] = fmaxf(b, 0.f);
    }
    __syncthreads();
    if (t < OUTC) {
        float c = b3[t];
#pragma unroll 8
        for (int k = 0; k < HID; k++) c += h2[k] * W3[k * OUTC + t];
        out[(size_t)s * OUTC + t] = c;
    }
}

// ---------------------------------------------------------------- launch
extern "C" void kernel_launch(void* const* d_in, const int* in_sizes, int n_in,
                              void* d_out, int out_size) {
    const float* feat   = (const float*)d_in[0];
    const float* coords = (const float*)d_in[1];
    const int*   ids    = (const int*)d_in[2];

    int wi = 3;
    if (n_in >= 8 && in_sizes[3] == 1) wi = 4;
    const float* W1 = (const float*)d_in[wi + 0];
    const float* W2 = (const float*)d_in[wi + 1];
    const float* W3 = (const float*)d_in[wi + 2];
    const float* b3 = (const float*)d_in[wi + 3];

    int n = in_sizes[0] / DFEAT;
    // chunk: per-block range, multiple of 4 for int4 hist/scatter
    int chunk = ((n + NB * 4 - 1) / (NB * 4)) * 4;

    float* out  = (float*)d_out;
    float* emb  = out;                           // [K, 256]
    float* cent = out + (size_t)KSEG * DFEAT;    // [K, 3]
    float* mlp  = cent + (size_t)KSEG * 3;       // [K, 32]
    (void)out_size;

    hist_kernel<<<NB, 256>>>(ids, n, chunk);
    segscan_kernel<<<KSEG, 256>>>();
    offscan_kernel<<<1, KSEG>>>();
    scatter_kernel<<<NB, 256>>>(ids, n, chunk);
    reduce_kernel<<<KSEG * SPLIT, 256>>>((const float4*)feat, coords);
    combine_kernel<<<KSEG, 256>>>(W1, W2, W3, b3, emb, cent, mlp);
}

// round 10
// speedup vs baseline: 1.1911x; 1.1699x over previous
#include <cuda_runtime.h>

#define KSEG 512
#define DFEAT 256
#define HID 64
#define OUTC 32
#define MAXN 1048576
#define NB   592          // hist/scatter blocks (4 per SM on 148 SMs)
#define SPLIT 4           // reduce CTAs per segment
#define CPT 3             // blocks per thread in seg-scan (ceil(592/256))

__device__ int g_blockhist[NB * KSEG];   // pass A: counts; pass B: per-(block,seg) base
__device__ int g_count[KSEG];
__device__ int g_offsets[KSEG + 1];
__device__ int g_perm[MAXN];
__device__ int g_done[KSEG];
__device__ float g_part[SPLIT * KSEG * DFEAT];   // feature partial sums
__device__ float g_cpart[SPLIT * KSEG * 3];      // coord partial sums

// ---------------------------------------------------------------- pass A: per-block histogram (int4)
__global__ void __launch_bounds__(256) hist_kernel(const int* __restrict__ ids, int n, int chunk) {
    __shared__ int sh[KSEG];
    for (int i = threadIdx.x; i < KSEG; i += 256) sh[i] = 0;
    __syncthreads();
    int b = blockIdx.x;
    if (b == 0)   // re-zero done counters every launch (graph replay)
        for (int i = threadIdx.x; i < KSEG; i += 256) g_done[i] = 0;
    int lo = b * chunk;                 // chunk is a multiple of 4
    int hi = min(lo + chunk, n);
    int nv = (hi - lo) >> 2;            // full int4s
    const int4* ids4 = (const int4*)(ids + lo);
    for (int i = threadIdx.x; i < nv; i += 256) {
        int4 v = ids4[i];
        if (v.x >= 0) atomicAdd(&sh[v.x], 1);
        if (v.y >= 0) atomicAdd(&sh[v.y], 1);
        if (v.z >= 0) atomicAdd(&sh[v.z], 1);
        if (v.w >= 0) atomicAdd(&sh[v.w], 1);
    }
    for (int i = lo + (nv << 2) + threadIdx.x; i < hi; i += 256) {
        int s = ids[i];
        if (s >= 0) atomicAdd(&sh[s], 1);
    }
    __syncthreads();
    for (int i = threadIdx.x; i < KSEG; i += 256)
        g_blockhist[b * KSEG + i] = sh[i];
}

// ---------------------------------------------------------------- pass B: per-segment scan over blocks
// grid = KSEG (1 CTA per segment), 256 threads, CPT blocks/thread. Writes g_count.
__global__ void __launch_bounds__(256) segscan_kernel() {
    int s = blockIdx.x;
    int t = threadIdx.x;
    int b0 = t * CPT;
    int v[CPT];
    int local = 0;
#pragma unroll
    for (int k = 0; k < CPT; k++) {
        int b = b0 + k;
        v[k] = (b < NB) ? g_blockhist[b * KSEG + s] : 0;
        local += v[k];
    }
    __shared__ int sh[256];
    sh[t] = local;
    __syncthreads();
    for (int off = 1; off < 256; off <<= 1) {
        int tmp = (t >= off) ? sh[t - off] : 0;
        int cur = sh[t];
        __syncthreads();
        sh[t] = cur + tmp;
        __syncthreads();
    }
    int run = sh[t] - local;   // exclusive prefix
#pragma unroll
    for (int k = 0; k < CPT; k++) {
        int b = b0 + k;
        if (b < NB) g_blockhist[b * KSEG + s] = run;
        run += v[k];
    }
    if (t == 255) g_count[s] = sh[255];
}

// ---------------------------------------------------------------- pass C: scatter (in-CTA offset scan)
// Each CTA redundantly scans g_count (L2-hot) in shared; block 0 publishes g_offsets.
__global__ void __launch_bounds__(256) scatter_kernel(const int* __restrict__ ids, int n, int chunk) {
    __shared__ int soff[KSEG];   // exclusive segment offsets
    __shared__ int spair[256];
    int t = threadIdx.x;
    int b = blockIdx.x;
    // thread t owns segments 2t, 2t+1
    int c0 = g_count[2 * t];
    int c1 = g_count[2 * t + 1];
    int pair = c0 + c1;
    spair[t] = pair;
    __syncthreads();
    for (int off = 1; off < 256; off <<= 1) {
        int tmp = (t >= off) ? spair[t - off] : 0;
        int cur = spair[t];
        __syncthreads();
        spair[t] = cur + tmp;
        __syncthreads();
    }
    int excl = spair[t] - pair;
    soff[2 * t]     = excl;
    soff[2 * t + 1] = excl + c0;
    __syncthreads();
    if (b == 0) {
        g_offsets[2 * t]     = soff[2 * t];
        g_offsets[2 * t + 1] = soff[2 * t + 1];
        if (t == 255) g_offsets[KSEG] = spair[255];
    }
    // cursors = segment offset + per-(block,seg) base
    __shared__ int cur[KSEG];
    for (int i = t; i < KSEG; i += 256)
        cur[i] = soff[i] + g_blockhist[b * KSEG + i];
    __syncthreads();
    int lo = b * chunk;
    int hi = min(lo + chunk, n);
    int nv = (hi - lo) >> 2;
    const int4* ids4 = (const int4*)(ids + lo);
    for (int i = t; i < nv; i += 256) {
        int4 v = ids4[i];
        int base = lo + (i << 2);
        if (v.x >= 0) g_perm[atomicAdd(&cur[v.x], 1)] = base;
        if (v.y >= 0) g_perm[atomicAdd(&cur[v.y], 1)] = base + 1;
        if (v.z >= 0) g_perm[atomicAdd(&cur[v.z], 1)] = base + 2;
        if (v.w >= 0) g_perm[atomicAdd(&cur[v.w], 1)] = base + 3;
    }
    for (int i = lo + (nv << 2) + t; i < hi; i += 256) {
        int s = ids[i];
        if (s >= 0) g_perm[atomicAdd(&cur[s], 1)] = i;
    }
}

// ---------------------------------------------------------------- split reduce + fused finalize/MLP
// grid = KSEG*SPLIT. 256 threads: 64 col-groups (float4) x 4 row slots, 4-deep unroll.
// Last part-CTA per segment (done-counter) performs combine + centroid + MLP.
__global__ void __launch_bounds__(256, 8) reduce_kernel(const float4* __restrict__ feat4,
                                                        const float* __restrict__ coords,
                                                        const float* __restrict__ W1,
                                                        const float* __restrict__ W2,
                                                        const float* __restrict__ W3,
                                                        const float* __restrict__ b3,
                                                        float* __restrict__ emb,
                                                        float* __restrict__ cent,
                                                        float* __restrict__ out) {
    int bid = blockIdx.x;
    int s = bid >> 2;          // segment
    int p = bid & (SPLIT - 1); // part
    int start = g_offsets[s];
    int end   = g_offsets[s + 1];
    int len   = end - start;
    int per   = (len + SPLIT - 1) / SPLIT;
    int lo = start + p * per;
    int hi = min(lo + per, end);

    int t  = threadIdx.x;
    int cg = t & 63;    // column group: cols [4cg, 4cg+3]
    int rs = t >> 6;    // row slot 0..3

    float4 acc = make_float4(0.f, 0.f, 0.f, 0.f);
    int j = lo + rs;
    for (; j + 12 < hi; j += 16) {
        int i0 = g_perm[j];
        int i1 = g_perm[j + 4];
        int i2 = g_perm[j + 8];
        int i3 = g_perm[j + 12];
        float4 v0 = __ldcs(&feat4[(size_t)i0 * 64 + cg]);
        float4 v1 = __ldcs(&feat4[(size_t)i1 * 64 + cg]);
        float4 v2 = __ldcs(&feat4[(size_t)i2 * 64 + cg]);
        float4 v3 = __ldcs(&feat4[(size_t)i3 * 64 + cg]);
        acc.x += (v0.x + v1.x) + (v2.x + v3.x);
        acc.y += (v0.y + v1.y) + (v2.y + v3.y);
        acc.z += (v0.z + v1.z) + (v2.z + v3.z);
        acc.w += (v0.w + v1.w) + (v2.w + v3.w);
    }
    for (; j < hi; j += 4) {
        int i0 = g_perm[j];
        float4 v0 = __ldcs(&feat4[(size_t)i0 * 64 + cg]);
        acc.x += v0.x; acc.y += v0.y; acc.z += v0.z; acc.w += v0.w;
    }

    __shared__ float4 shv[256];
    shv[t] = acc;
    __syncthreads();
    if (rs == 0) {
        float4 a = shv[cg], b = shv[cg + 64], c = shv[cg + 128], d = shv[cg + 192];
        float4 r;
        r.x = (a.x + b.x) + (c.x + d.x);
        r.y = (a.y + b.y) + (c.y + d.y);
        r.z = (a.z + b.z) + (c.z + d.z);
        r.w = (a.w + b.w) + (c.w + d.w);
        ((float4*)g_part)[((size_t)p * KSEG + s) * 64 + cg] = r;
    }

    // coords partial
    float cx = 0.f, cy = 0.f, cz = 0.f;
    for (int jj = lo + t; jj < hi; jj += 256) {
        int i = g_perm[jj];
        cx += coords[3 * (size_t)i + 0];
        cy += coords[3 * (size_t)i + 1];
        cz += coords[3 * (size_t)i + 2];
    }
    __shared__ float shx[256], shy[256], shz[256];
    shx[t] = cx; shy[t] = cy; shz[t] = cz;
    __syncthreads();
    for (int off = 128; off > 0; off >>= 1) {
        if (t < off) {
            shx[t] += shx[t + off];
            shy[t] += shy[t + off];
            shz[t] += shz[t + off];
        }
        __syncthreads();
    }
    if (t == 0) {
        g_cpart[((size_t)p * KSEG + s) * 3 + 0] = shx[0];
        g_cpart[((size_t)p * KSEG + s) * 3 + 1] = shy[0];
        g_cpart[((size_t)p * KSEG + s) * 3 + 2] = shz[0];
    }

    // ---- last-block-done finalize ----
    __shared__ int slast;
    __threadfence();
    __syncthreads();
    if (t == 0) slast = (atomicAdd(&g_done[s], 1) == SPLIT - 1) ? 1 : 0;
    __syncthreads();
    if (!slast) return;

    float denom = 1.0f / (float)(len > 0 ? len : 1);
    __shared__ float e[DFEAT];
    float v = 0.f;
#pragma unroll
    for (int q = 0; q < SPLIT; q++)
        v += g_part[((size_t)q * KSEG + s) * DFEAT + t];
    v *= denom;
    e[t] = v;
    emb[(size_t)s * DFEAT + t] = v;

    if (t < 3) {
        float c = 0.f;
#pragma unroll
        for (int q = 0; q < SPLIT; q++)
            c += g_cpart[((size_t)q * KSEG + s) * 3 + t];
        cent[s * 3 + t] = c * denom;
    }
    __syncthreads();

    __shared__ float h1[HID];
    __shared__ float h2[HID];
    if (t < HID) {
        float a = 0.f;
#pragma unroll 8
        for (int k = 0; k < DFEAT; k++) a += e[k] * W1[k * HID + t];
        h1[t] = fmaxf(a, 0.f);
    }
    __syncthreads();
    if (t < HID) {
        float b = 0.f;
#pragma unroll 8
        for (int k = 0; k < HID; k++) b += h1[k] * W2[k * HID + t];
        h2[t] = fmaxf(b, 0.f);
    }
    __syncthreads();
    if (t < OUTC) {
        float c = b3[t];
#pragma unroll 8
        for (int k = 0; k < HID; k++) c += h2[k] * W3[k * OUTC + t];
        out[(size_t)s * OUTC + t] = c;
    }
}

// ---------------------------------------------------------------- launch
extern "C" void kernel_launch(void* const* d_in, const int* in_sizes, int n_in,
                              void* d_out, int out_size) {
    const float* feat   = (const float*)d_in[0];
    const float* coords = (const float*)d_in[1];
    const int*   ids    = (const int*)d_in[2];

    int wi = 3;
    if (n_in >= 8 && in_sizes[3] == 1) wi = 4;
    const float* W1 = (const float*)d_in[wi + 0];
    const float* W2 = (const float*)d_in[wi + 1];
    const float* W3 = (const float*)d_in[wi + 2];
    const float* b3 = (const float*)d_in[wi + 3];

    int n = in_sizes[0] / DFEAT;
    int chunk = ((n + NB * 4 - 1) / (NB * 4)) * 4;   // multiple of 4 for int4

    float* out  = (float*)d_out;
    float* emb  = out;                           // [K, 256]
    float* cent = out + (size_t)KSEG * DFEAT;    // [K, 3]
    float* mlp  = cent + (size_t)KSEG * 3;       // [K, 32]
    (void)out_size;

    hist_kernel<<<NB, 256>>>(ids, n, chunk);
    segscan_kernel<<<KSEG, 256>>>();
    scatter_kernel<<<NB, 256>>>(ids, n, chunk);
    reduce_kernel<<<KSEG * SPLIT, 256>>>((const float4*)feat, coords,
                                         W1, W2, W3, b3, emb, cent, mlp);
}